// round 5
// baseline (speedup 1.0000x reference)
#include <cuda_runtime.h>
#include <cstdint>

// CrossNet closed form, TMA bulk I/O version.
//   out = m*x + k1*b1 + k2*b2 + b3
//   d_k = x . w_k ;  c12=b1.w2, c13=b1.w3, c23=b2.w3 (computed in-CTA)
//   a1 = d1+1; a2 = a1*d2 + c12 + 1; a3 = a2*(a1*d3 + c13) + c23 + 1
//   k2 = a3; k1 = a2*a3; m = a1*k1
// B=16384, D=2048, fp32. R=4 rows/CTA, 512 threads.
// Row data moves via cp.async.bulk (gmem<->smem), bypassing per-thread
// LDG/STG wavefronts that saturated the L1tex queue in earlier rounds.

#define D 2048
#define VEC (D / 4)          // 512 float4 per row
#define THREADS 512
#define NWARP (THREADS / 32) // 16
#define R 4
#define TILE_BYTES (R * D * 4)   // 32768

__device__ __forceinline__ uint32_t smem_u32(const void* p) {
    uint32_t a;
    asm("{ .reg .u64 t; cvta.to.shared.u64 t, %1; cvt.u32.u64 %0, t; }"
        : "=r"(a) : "l"(p));
    return a;
}

__global__ __launch_bounds__(THREADS, 3)
void crossnet_kernel(const float4* __restrict__ x,
                     const float4* __restrict__ w1, const float4* __restrict__ b1,
                     const float4* __restrict__ w2, const float4* __restrict__ b2,
                     const float4* __restrict__ w3, const float4* __restrict__ b3,
                     float4* __restrict__ out)
{
    __shared__ alignas(128) float4 sx[R * VEC];                 // 32 KB tile
    __shared__ float4 sh_p1[NWARP], sh_p2[NWARP], sh_p3[NWARP]; // per-warp dot partials
    __shared__ float4 sh_q[NWARP];                              // per-warp (c12,c13,c23,_)
    __shared__ float4 sh_c[R];                                  // per-row (m,k1,k2,_)
    __shared__ alignas(8) unsigned long long mbar;

    const int t    = threadIdx.x;
    const int lane = t & 31;
    const int wid  = t >> 5;
    const uint32_t mbar_a = smem_u32(&mbar);
    const uint32_t sx_a   = smem_u32(sx);

    const char* gsrc = (const char*)x   + (size_t)blockIdx.x * TILE_BYTES;
    char*       gdst = (char*)out       + (size_t)blockIdx.x * TILE_BYTES;

    // ---- kick off bulk load of 4 rows (one thread) ----
    if (t == 0) {
        asm volatile("mbarrier.init.shared.b64 [%0], 1;" :: "r"(mbar_a) : "memory");
    }
    __syncthreads();
    if (t == 0) {
        asm volatile("mbarrier.arrive.expect_tx.shared.b64 _, [%0], %1;"
                     :: "r"(mbar_a), "r"((uint32_t)TILE_BYTES) : "memory");
        asm volatile("cp.async.bulk.shared::cta.global.mbarrier::complete_tx::bytes "
                     "[%0], [%1], %2, [%3];"
                     :: "r"(sx_a), "l"(gsrc), "r"((uint32_t)TILE_BYTES), "r"(mbar_a)
                     : "memory");
    }

    // ---- overlap with TMA: load w/b, compute cross-constant partials ----
    const float4 wv1 = __ldg(&w1[t]);
    const float4 wv2 = __ldg(&w2[t]);
    const float4 wv3 = __ldg(&w3[t]);
    const float4 bv1 = __ldg(&b1[t]);
    const float4 bv2 = __ldg(&b2[t]);

    float q12 = bv1.x*wv2.x + bv1.y*wv2.y + bv1.z*wv2.z + bv1.w*wv2.w;
    float q13 = bv1.x*wv3.x + bv1.y*wv3.y + bv1.z*wv3.z + bv1.w*wv3.w;
    float q23 = bv2.x*wv3.x + bv2.y*wv3.y + bv2.z*wv3.z + bv2.w*wv3.w;
    #pragma unroll
    for (int off = 16; off > 0; off >>= 1) {
        q12 += __shfl_xor_sync(0xFFFFFFFFu, q12, off);
        q13 += __shfl_xor_sync(0xFFFFFFFFu, q13, off);
        q23 += __shfl_xor_sync(0xFFFFFFFFu, q23, off);
    }
    if (lane == 0) sh_q[wid] = make_float4(q12, q13, q23, 0.0f);

    // ---- wait for tile ----
    {
        uint32_t done;
        do {
            asm volatile(
                "{\n .reg .pred P;\n"
                " mbarrier.try_wait.parity.acquire.cta.shared::cta.b64 P, [%1], %2, 0x989680;\n"
                " selp.b32 %0, 1, 0, P;\n}"
                : "=r"(done) : "r"(mbar_a), "r"(0u) : "memory");
        } while (!done);
    }

    // ---- read rows into registers (conflict-free), three dots ----
    float4 y[R];
    #pragma unroll
    for (int r = 0; r < R; ++r)
        y[r] = sx[r * VEC + t];

    float p1[R], p2[R], p3[R];
    #pragma unroll
    for (int r = 0; r < R; ++r) {
        p1[r] = y[r].x*wv1.x + y[r].y*wv1.y + y[r].z*wv1.z + y[r].w*wv1.w;
        p2[r] = y[r].x*wv2.x + y[r].y*wv2.y + y[r].z*wv2.z + y[r].w*wv2.w;
        p3[r] = y[r].x*wv3.x + y[r].y*wv3.y + y[r].z*wv3.z + y[r].w*wv3.w;
    }
    #pragma unroll
    for (int off = 16; off > 0; off >>= 1) {
        #pragma unroll
        for (int r = 0; r < R; ++r) {
            p1[r] += __shfl_xor_sync(0xFFFFFFFFu, p1[r], off);
            p2[r] += __shfl_xor_sync(0xFFFFFFFFu, p2[r], off);
            p3[r] += __shfl_xor_sync(0xFFFFFFFFu, p3[r], off);
        }
    }
    if (lane == 0) {
        sh_p1[wid] = make_float4(p1[0], p1[1], p1[2], p1[3]);
        sh_p2[wid] = make_float4(p2[0], p2[1], p2[2], p2[3]);
        sh_p3[wid] = make_float4(p3[0], p3[1], p3[2], p3[3]);
    }
    __syncthreads();

    // ---- warp0: cross-warp reduce + coefficients ----
    if (wid == 0) {
        const bool ok = lane < NWARP;
        float4 z = make_float4(0.f, 0.f, 0.f, 0.f);
        float4 v1 = ok ? sh_p1[lane] : z;
        float4 v2 = ok ? sh_p2[lane] : z;
        float4 v3 = ok ? sh_p3[lane] : z;
        float4 vq = ok ? sh_q[lane]  : z;
        #pragma unroll
        for (int off = 8; off > 0; off >>= 1) {
            v1.x += __shfl_xor_sync(0xFFFFFFFFu, v1.x, off);
            v1.y += __shfl_xor_sync(0xFFFFFFFFu, v1.y, off);
            v1.z += __shfl_xor_sync(0xFFFFFFFFu, v1.z, off);
            v1.w += __shfl_xor_sync(0xFFFFFFFFu, v1.w, off);
            v2.x += __shfl_xor_sync(0xFFFFFFFFu, v2.x, off);
            v2.y += __shfl_xor_sync(0xFFFFFFFFu, v2.y, off);
            v2.z += __shfl_xor_sync(0xFFFFFFFFu, v2.z, off);
            v2.w += __shfl_xor_sync(0xFFFFFFFFu, v2.w, off);
            v3.x += __shfl_xor_sync(0xFFFFFFFFu, v3.x, off);
            v3.y += __shfl_xor_sync(0xFFFFFFFFu, v3.y, off);
            v3.z += __shfl_xor_sync(0xFFFFFFFFu, v3.z, off);
            v3.w += __shfl_xor_sync(0xFFFFFFFFu, v3.w, off);
            vq.x += __shfl_xor_sync(0xFFFFFFFFu, vq.x, off);
            vq.y += __shfl_xor_sync(0xFFFFFFFFu, vq.y, off);
            vq.z += __shfl_xor_sync(0xFFFFFFFFu, vq.z, off);
        }
        if (lane == 0) {
            const float c12 = vq.x, c13 = vq.y, c23 = vq.z;
            const float d1[R] = {v1.x, v1.y, v1.z, v1.w};
            const float d2[R] = {v2.x, v2.y, v2.z, v2.w};
            const float d3[R] = {v3.x, v3.y, v3.z, v3.w};
            #pragma unroll
            for (int r = 0; r < R; ++r) {
                const float a1 = d1[r] + 1.0f;
                const float a2 = fmaf(a1, d2[r], c12) + 1.0f;
                const float a3 = fmaf(a2, fmaf(a1, d3[r], c13), c23) + 1.0f;
                const float k1 = a2 * a3;
                const float m  = a1 * k1;
                sh_c[r] = make_float4(m, k1, a3, 0.0f);
            }
        }
    }
    __syncthreads();

    // ---- epilogue: out = m*x + k1*b1 + k2*b2 + b3, written in-place to smem ----
    const float4 bv3 = __ldg(&b3[t]);
    #pragma unroll
    for (int r = 0; r < R; ++r) {
        const float4 c = sh_c[r];
        float4 o;
        o.x = fmaf(y[r].x, c.x, fmaf(bv1.x, c.y, fmaf(bv2.x, c.z, bv3.x)));
        o.y = fmaf(y[r].y, c.x, fmaf(bv1.y, c.y, fmaf(bv2.y, c.z, bv3.y)));
        o.z = fmaf(y[r].z, c.x, fmaf(bv1.z, c.y, fmaf(bv2.z, c.z, bv3.z)));
        o.w = fmaf(y[r].w, c.x, fmaf(bv1.w, c.y, fmaf(bv2.w, c.z, bv3.w)));
        sx[r * VEC + t] = o;
    }

    // ---- bulk store tile back ----
    __syncthreads();
    if (t == 0) {
        asm volatile("fence.proxy.async.shared::cta;" ::: "memory");
        asm volatile("cp.async.bulk.global.shared::cta.bulk_group [%0], [%1], %2;"
                     :: "l"(gdst), "r"(sx_a), "r"((uint32_t)TILE_BYTES) : "memory");
        asm volatile("cp.async.bulk.commit_group;" ::: "memory");
        asm volatile("cp.async.bulk.wait_group 0;" ::: "memory");
    }
}

extern "C" void kernel_launch(void* const* d_in, const int* in_sizes, int n_in,
                              void* d_out, int out_size)
{
    const float4* x  = (const float4*)d_in[0];
    const float4* w1 = (const float4*)d_in[1];
    const float4* b1 = (const float4*)d_in[2];
    const float4* w2 = (const float4*)d_in[3];
    const float4* b2 = (const float4*)d_in[4];
    const float4* w3 = (const float4*)d_in[5];
    const float4* b3 = (const float4*)d_in[6];
    float4* out = (float4*)d_out;

    const int B = in_sizes[0] / D;   // 16384
    crossnet_kernel<<<B / R, THREADS>>>(x, w1, b1, w2, b2, w3, b3, out);
}

// round 7
// speedup vs baseline: 1.3399x; 1.3399x over previous
#include <cuda_runtime.h>

// CrossNet closed form, persistent CTAs + cross-tile software pipeline.
//   d_k = x . w_k ; c12=b1.w2, c13=b1.w3, c23=b2.w3 (prologue, per CTA)
//   a1 = d1+1; a2 = a1*d2+c12+1; a3 = a2*(a1*d3+c13)+c23+1
//   out = (a1*a2*a3)*x + (a2*a3)*b1 + a3*b2 + b3
// B=16384, D=2048 fp32. R=4 rows/tile, 512 threads, 296 persistent CTAs.
// Next tile's loads are issued BEFORE the current tile's reduction so DRAM
// stays busy through the barrier-synchronized compute phases.

#define D 2048
#define VEC (D / 4)          // 512 float4 per row
#define THREADS 512
#define NWARP (THREADS / 32) // 16
#define R 4
#define NCTA 296             // 2 per SM * 148 SMs

__device__ __forceinline__ float dot4(float4 a, float4 b) {
    return a.x*b.x + a.y*b.y + a.z*b.z + a.w*b.w;
}

__global__ __launch_bounds__(THREADS, 2)
void crossnet_kernel(const float4* __restrict__ x,
                     const float4* __restrict__ w1, const float4* __restrict__ b1,
                     const float4* __restrict__ w2, const float4* __restrict__ b2,
                     const float4* __restrict__ w3, const float4* __restrict__ b3,
                     float4* __restrict__ out, int ntiles)
{
    __shared__ float4 shp1[NWARP], shp2[NWARP], shp3[NWARP]; // per-warp dot partials (4 rows)
    __shared__ float4 sh_c[R];                               // per-row (m, k1, k2, _)
    __shared__ float  sh_k[3];                               // c12, c13, c23

    const int t    = threadIdx.x;
    const int lane = t & 31;
    const int wid  = t >> 5;

    // ---- prologue: cross constants c12=b1.w2, c13=b1.w3, c23=b2.w3 ----
    {
        const float4 bq1 = __ldg(&b1[t]);
        const float4 bq2 = __ldg(&b2[t]);
        const float4 wq2 = __ldg(&w2[t]);
        const float4 wq3 = __ldg(&w3[t]);
        float q12 = dot4(bq1, wq2);
        float q13 = dot4(bq1, wq3);
        float q23 = dot4(bq2, wq3);
        #pragma unroll
        for (int off = 16; off > 0; off >>= 1) {
            q12 += __shfl_xor_sync(0xFFFFFFFFu, q12, off);
            q13 += __shfl_xor_sync(0xFFFFFFFFu, q13, off);
            q23 += __shfl_xor_sync(0xFFFFFFFFu, q23, off);
        }
        if (lane == 0) shp1[wid] = make_float4(q12, q13, q23, 0.0f);
    }
    __syncthreads();
    if (wid == 0) {
        float4 v = (lane < NWARP) ? shp1[lane] : make_float4(0.f, 0.f, 0.f, 0.f);
        #pragma unroll
        for (int off = 8; off > 0; off >>= 1) {
            v.x += __shfl_xor_sync(0xFFFFFFFFu, v.x, off);
            v.y += __shfl_xor_sync(0xFFFFFFFFu, v.y, off);
            v.z += __shfl_xor_sync(0xFFFFFFFFu, v.z, off);
        }
        if (lane == 0) { sh_k[0] = v.x; sh_k[1] = v.y; sh_k[2] = v.z; }
    }

    // ---- pipeline prologue: load first tile ----
    int tile = blockIdx.x;
    float4 yc[R];
    if (tile < ntiles) {
        const int base = tile * (R * VEC) + t;
        #pragma unroll
        for (int r = 0; r < R; ++r)
            yc[r] = __ldcs(&x[base + r * VEC]);
    }
    __syncthreads();   // shp1 prologue reads done before loop overwrites it

    for (; tile < ntiles; tile += gridDim.x) {
        // ---- issue NEXT tile's loads first (keeps DRAM busy during reduce) ----
        const int nxt = tile + gridDim.x;
        float4 yn[R];
        if (nxt < ntiles) {
            const int nbase = nxt * (R * VEC) + t;
            #pragma unroll
            for (int r = 0; r < R; ++r)
                yn[r] = __ldcs(&x[nbase + r * VEC]);
        }

        // ---- three dots on current tile, batched to cap register pressure ----
        {
            const float4 wv = __ldg(&w1[t]);
            float p[R];
            #pragma unroll
            for (int r = 0; r < R; ++r) p[r] = dot4(yc[r], wv);
            #pragma unroll
            for (int off = 16; off > 0; off >>= 1) {
                #pragma unroll
                for (int r = 0; r < R; ++r)
                    p[r] += __shfl_xor_sync(0xFFFFFFFFu, p[r], off);
            }
            if (lane == 0) shp1[wid] = make_float4(p[0], p[1], p[2], p[3]);
        }
        {
            const float4 wv = __ldg(&w2[t]);
            float p[R];
            #pragma unroll
            for (int r = 0; r < R; ++r) p[r] = dot4(yc[r], wv);
            #pragma unroll
            for (int off = 16; off > 0; off >>= 1) {
                #pragma unroll
                for (int r = 0; r < R; ++r)
                    p[r] += __shfl_xor_sync(0xFFFFFFFFu, p[r], off);
            }
            if (lane == 0) shp2[wid] = make_float4(p[0], p[1], p[2], p[3]);
        }
        {
            const float4 wv = __ldg(&w3[t]);
            float p[R];
            #pragma unroll
            for (int r = 0; r < R; ++r) p[r] = dot4(yc[r], wv);
            #pragma unroll
            for (int off = 16; off > 0; off >>= 1) {
                #pragma unroll
                for (int r = 0; r < R; ++r)
                    p[r] += __shfl_xor_sync(0xFFFFFFFFu, p[r], off);
            }
            if (lane == 0) shp3[wid] = make_float4(p[0], p[1], p[2], p[3]);
        }
        __syncthreads();

        // ---- warp0: cross-warp combine + coefficients ----
        if (wid == 0) {
            const float4 z = make_float4(0.f, 0.f, 0.f, 0.f);
            float4 v1 = (lane < NWARP) ? shp1[lane] : z;
            float4 v2 = (lane < NWARP) ? shp2[lane] : z;
            float4 v3 = (lane < NWARP) ? shp3[lane] : z;
            #pragma unroll
            for (int off = 8; off > 0; off >>= 1) {
                v1.x += __shfl_xor_sync(0xFFFFFFFFu, v1.x, off);
                v1.y += __shfl_xor_sync(0xFFFFFFFFu, v1.y, off);
                v1.z += __shfl_xor_sync(0xFFFFFFFFu, v1.z, off);
                v1.w += __shfl_xor_sync(0xFFFFFFFFu, v1.w, off);
                v2.x += __shfl_xor_sync(0xFFFFFFFFu, v2.x, off);
                v2.y += __shfl_xor_sync(0xFFFFFFFFu, v2.y, off);
                v2.z += __shfl_xor_sync(0xFFFFFFFFu, v2.z, off);
                v2.w += __shfl_xor_sync(0xFFFFFFFFu, v2.w, off);
                v3.x += __shfl_xor_sync(0xFFFFFFFFu, v3.x, off);
                v3.y += __shfl_xor_sync(0xFFFFFFFFu, v3.y, off);
                v3.z += __shfl_xor_sync(0xFFFFFFFFu, v3.z, off);
                v3.w += __shfl_xor_sync(0xFFFFFFFFu, v3.w, off);
            }
            if (lane == 0) {
                const float c12 = sh_k[0], c13 = sh_k[1], c23 = sh_k[2];
                const float d1[R] = {v1.x, v1.y, v1.z, v1.w};
                const float d2[R] = {v2.x, v2.y, v2.z, v2.w};
                const float d3[R] = {v3.x, v3.y, v3.z, v3.w};
                #pragma unroll
                for (int r = 0; r < R; ++r) {
                    const float a1 = d1[r] + 1.0f;
                    const float a2 = fmaf(a1, d2[r], c12) + 1.0f;
                    const float a3 = fmaf(a2, fmaf(a1, d3[r], c13), c23) + 1.0f;
                    const float k1 = a2 * a3;
                    const float m  = a1 * k1;
                    sh_c[r] = make_float4(m, k1, a3, 0.0f);
                }
            }
        }
        __syncthreads();

        // ---- epilogue: out = m*x + k1*b1 + k2*b2 + b3 ----
        const float4 bv1 = __ldg(&b1[t]);
        const float4 bv2 = __ldg(&b2[t]);
        const float4 bv3 = __ldg(&b3[t]);
        const int base = tile * (R * VEC) + t;
        #pragma unroll
        for (int r = 0; r < R; ++r) {
            const float4 c = sh_c[r];
            float4 o;
            o.x = fmaf(yc[r].x, c.x, fmaf(bv1.x, c.y, fmaf(bv2.x, c.z, bv3.x)));
            o.y = fmaf(yc[r].y, c.x, fmaf(bv1.y, c.y, fmaf(bv2.y, c.z, bv3.y)));
            o.z = fmaf(yc[r].z, c.x, fmaf(bv1.z, c.y, fmaf(bv2.z, c.z, bv3.z)));
            o.w = fmaf(yc[r].w, c.x, fmaf(bv1.w, c.y, fmaf(bv2.w, c.z, bv3.w)));
            __stcs(&out[base + r * VEC], o);
        }

        // ---- rotate pipeline ----
        #pragma unroll
        for (int r = 0; r < R; ++r) yc[r] = yn[r];
    }
}

extern "C" void kernel_launch(void* const* d_in, const int* in_sizes, int n_in,
                              void* d_out, int out_size)
{
    const float4* x  = (const float4*)d_in[0];
    const float4* w1 = (const float4*)d_in[1];
    const float4* b1 = (const float4*)d_in[2];
    const float4* w2 = (const float4*)d_in[3];
    const float4* b2 = (const float4*)d_in[4];
    const float4* w3 = (const float4*)d_in[5];
    const float4* b3 = (const float4*)d_in[6];
    float4* out = (float4*)d_out;

    const int B = in_sizes[0] / D;    // 16384
    const int ntiles = B / R;         // 4096
    const int grid = (ntiles < NCTA) ? ntiles : NCTA;
    crossnet_kernel<<<grid, THREADS>>>(x, w1, b1, w2, b2, w3, b3, out, ntiles);
}